// round 1
// baseline (speedup 1.0000x reference)
#include <cuda_runtime.h>

#define BATCH 2048
#define IN 256
#define OUT 256
#define OT 16   // outputs per block
#define BT 16   // batches per block

// Folded affine coefficients: postact = c1*x + c0
__device__ float g_c1[OUT * IN];
__device__ float g_c0[OUT * IN];

__global__ __launch_bounds__(256) void kan_precompute(const float* __restrict__ affine,
                                                      const float* __restrict__ mask) {
    int idx = blockIdx.x * blockDim.x + threadIdx.x;  // 0 .. OUT*IN-1
    float4 a = reinterpret_cast<const float4*>(affine)[idx];  // (a0,a1,a2,a3)
    float m = mask[idx];
    g_c1[idx] = m * a.z * a.x;
    g_c0[idx] = m * (a.z * a.y + a.w);
}

__global__ __launch_bounds__(256) void kan_main(const float* __restrict__ x,
                                                float* __restrict__ y,
                                                float* __restrict__ post) {
    __shared__ float4 xs[BT * (IN / 4)];  // 16 batches x 64 float4 = 16 KB

    const int t = threadIdx.x;
    const int o_loc = t >> 4;      // 0..15 (lanes 0-15 of a warp share one o, 16-31 the next)
    const int lane = t & 15;       // 0..15
    const int o = blockIdx.y * OT + o_loc;
    const int b0 = blockIdx.x * BT;

    // Hoist this thread's c1/c0 slice (16 inputs) into registers — reused for all BT batches.
    float4 c1r[4], c0r[4];
#pragma unroll
    for (int k = 0; k < 4; k++) {
        int f = lane + 16 * k;  // float4 index within the 64 of this output row
        c1r[k] = reinterpret_cast<const float4*>(g_c1)[o * (IN / 4) + f];
        c0r[k] = reinterpret_cast<const float4*>(g_c0)[o * (IN / 4) + f];
    }

    // Cooperative load of the x tile (BT*IN floats = 1024 float4s, 4 per thread).
    const float4* xg = reinterpret_cast<const float4*>(x + (size_t)b0 * IN);
#pragma unroll
    for (int j = 0; j < 4; j++) xs[t + 256 * j] = xg[t + 256 * j];
    __syncthreads();

#pragma unroll 4
    for (int bl = 0; bl < BT; bl++) {
        const int b = b0 + bl;
        float4* prow = reinterpret_cast<float4*>(post + ((size_t)b * OUT + o) * IN);
        float acc = 0.0f;
#pragma unroll
        for (int k = 0; k < 4; k++) {
            float4 xv = xs[bl * (IN / 4) + lane + 16 * k];
            float4 p;
            p.x = fmaf(c1r[k].x, xv.x, c0r[k].x);
            p.y = fmaf(c1r[k].y, xv.y, c0r[k].y);
            p.z = fmaf(c1r[k].z, xv.z, c0r[k].z);
            p.w = fmaf(c1r[k].w, xv.w, c0r[k].w);
            acc += (p.x + p.y) + (p.z + p.w);
            // 16 lanes with consecutive f write a contiguous 256B run -> fully coalesced.
            __stcs(&prow[lane + 16 * k], p);
        }
        // Reduce acc across the 16 lanes sharing this output.
#pragma unroll
        for (int off = 8; off; off >>= 1)
            acc += __shfl_xor_sync(0xffffffffu, acc, off);
        if (lane == 0) y[(size_t)b * OUT + o] = acc;
    }
}

extern "C" void kernel_launch(void* const* d_in, const int* in_sizes, int n_in,
                              void* d_out, int out_size) {
    const float* x      = (const float*)d_in[0];  // [2048, 256]
    const float* affine = (const float*)d_in[1];  // [256, 256, 4]
    const float* mask   = (const float*)d_in[2];  // [256, 256]

    // Output layout: y [2048*256] followed by postacts [2048*256*256]
    float* y    = (float*)d_out;
    float* post = (float*)d_out + (size_t)BATCH * OUT;

    kan_precompute<<<(OUT * IN) / 256, 256>>>(affine, mask);

    dim3 grid(BATCH / BT, OUT / OT);
    kan_main<<<grid, 256>>>(x, y, post);
}